// round 17
// baseline (speedup 1.0000x reference)
#include <cuda_runtime.h>

#define LOG2E 1.4426950408889634f
typedef unsigned long long u64;

// ---------------- scratch (device globals; no allocation allowed) -------------
__device__ float g_k[32 * 2 * 2048];     // [c][b][n]           (raw)
__device__ float g_q[32 * 2048 * 2];     // [c][n][b]           (pre-scaled by LOG2E)
__device__ float g_v[32 * 2048 * 2];     // [c][n][b]
__device__ float g_vz[32 * 2048 * 2];    // v * (1/Z) per column
__device__ float g_nm[32 * 2048];        // -(box-bound max log2-logit) per (c,m)
__device__ float g_attn[32 * 2048 * 2];  // flat [C,N,B] attention output

// ---------------- f32x2 helpers (sm_100+) ------------------------------------
__device__ __forceinline__ u64 pk2(float lo, float hi) {
    u64 r; asm("mov.b64 %0, {%1, %2};" : "=l"(r) : "f"(lo), "f"(hi)); return r;
}
__device__ __forceinline__ void upk2(float& lo, float& hi, u64 v) {
    asm("mov.b64 {%0, %1}, %2;" : "=f"(lo), "=f"(hi) : "l"(v));
}
__device__ __forceinline__ u64 fma2(u64 a, u64 b, u64 c) {
    u64 r; asm("fma.rn.f32x2 %0, %1, %2, %3;" : "=l"(r) : "l"(a), "l"(b), "l"(c)); return r;
}

// =============================================================================
// Kernel 0: init biases into qkv scratch, out = x + b_alter, zero g_attn.
// =============================================================================
__global__ __launch_bounds__(256) void init_kernel(
    const float* __restrict__ x,
    const float* __restrict__ bk, const float* __restrict__ bq,
    const float* __restrict__ bv, const float* __restrict__ ba,
    float* __restrict__ out)
{
    const int i = blockIdx.x * 256 + threadIdx.x;   // 512 blocks -> 131072 threads
    if (i < 131072) {
        const int c = i >> 12;
        g_k[i] = bk[c];
        g_q[i] = bq[c] * LOG2E;
        g_v[i] = bv[c];
    }
    for (int j = i; j < 262144; j += 131072) {
        const int co = (j >> 11) & 63;
        out[j] = x[j] + ba[co];
        g_attn[j] = 0.f;
    }
}

// =============================================================================
// Kernel A: conv3d key/query/value (64 -> 3x32 ch, 3x3x3, pad 1), split-K x8.
// CO-QUAD: thread computes 4 adjacent output channels inside ONE conv (which
// = blockIdx.x). 9 LDS + 8 O-packs feed 96 fma2 per (kd,kh).
// Precomputed fill indices, double-buffered tile, 1 barrier per ci.
// grid (which=3, d=8, z=16: b*8+s), 128 threads = 8 slots x 16 h.
// =============================================================================
__global__ __launch_bounds__(128) void conv_qkv_kernel(
    const float* __restrict__ x,
    const float* __restrict__ wk, const float* __restrict__ wq,
    const float* __restrict__ wv)
{
    __shared__ float tile[2][1080];
    const int t     = threadIdx.x;
    const int which = blockIdx.x;         // 0=key 1=query 2=value
    const int d     = blockIdx.y;
    const int b     = blockIdx.z >> 3;
    const int s     = blockIdx.z & 7;     // ci chunk: [8s, 8s+8)
    const int c0    = (t >> 4) * 4;       // 0..28, quad of channels
    const int h     = t & 15;

    int  si[8], gb[8];
    #pragma unroll
    for (int j = 0; j < 8; j++) {
        const int i = t + j * 128;
        si[j] = 1078; gb[j] = 0;
        if (i < 972) {
            const int dd = i / 324, r = i % 324, hh = r / 18, ww = r % 18;
            const int gd = d + dd - 1, gh = hh - 1, gw = ww - 1;
            si[j] = dd * 360 + hh * 20 + ww;
            if ((unsigned)gd < 8u && (unsigned)gh < 16u && (unsigned)gw < 16u)
                gb[j] = (b * 64 + s * 8) * 2048 + gd * 256 + gh * 16 + gw + 1;
        }
    }

    const float* W = (which == 0) ? wk : (which == 1 ? wq : wv);
    u64 acc[4][8];
    #pragma unroll
    for (int q = 0; q < 4; q++)
        #pragma unroll
        for (int p = 0; p < 8; p++) acc[q][p] = pk2(0.f, 0.f);
    const float* Wb = W + c0 * 1728 + s * 8 * 27;   // 64*27 = 1728 per channel

    #pragma unroll
    for (int j = 0; j < 8; j++)
        tile[0][si[j]] = gb[j] ? x[gb[j] - 1] : 0.f;
    __syncthreads();

    for (int ci = 0; ci < 8; ci++) {
        const int cur = ci & 1;
        float r[8];
        if (ci < 7) {
            const int off = (ci + 1) * 2048 - 1;
            #pragma unroll
            for (int j = 0; j < 8; j++)
                r[j] = gb[j] ? x[gb[j] + off] : 0.f;
        }

        #pragma unroll
        for (int kd = 0; kd < 3; kd++) {
            #pragma unroll
            for (int kh = 0; kh < 3; kh++) {
                const float* row = &tile[cur][kd * 360 + (h + kh) * 20];
                u64 E[9], O[8];
                #pragma unroll
                for (int p = 0; p < 9; p++)
                    E[p] = *(const u64*)(row + 2 * p);
                #pragma unroll
                for (int p = 0; p < 8; p++) {
                    float elo, ehi, flo, fhi;
                    upk2(elo, ehi, E[p]);
                    upk2(flo, fhi, E[p + 1]);
                    O[p] = pk2(ehi, flo);
                }
                const int kb = ci * 27 + (kd * 3 + kh) * 3;
                #pragma unroll
                for (int q = 0; q < 4; q++) {
                    const float* Wq = Wb + q * 1728 + kb;
                    const u64 Q0 = pk2(Wq[0], Wq[0]);
                    const u64 Q1 = pk2(Wq[1], Wq[1]);
                    const u64 Q2 = pk2(Wq[2], Wq[2]);
                    #pragma unroll
                    for (int p = 0; p < 8; p++) {
                        acc[q][p] = fma2(Q0, E[p], acc[q][p]);
                        acc[q][p] = fma2(Q1, O[p], acc[q][p]);
                        acc[q][p] = fma2(Q2, E[p + 1], acc[q][p]);
                    }
                }
            }
        }

        if (ci < 7) {
            #pragma unroll
            for (int j = 0; j < 8; j++)
                tile[cur ^ 1][si[j]] = r[j];
        }
        __syncthreads();
    }

    const int nbase = d * 256 + h * 16;
    if (which == 0) {
        #pragma unroll
        for (int q = 0; q < 4; q++)
            #pragma unroll
            for (int p = 0; p < 8; p++) {
                float a, bb;
                upk2(a, bb, acc[q][p]);
                float* dst = &g_k[((c0 + q) * 2 + b) * 2048 + nbase + 2 * p];
                asm volatile("red.global.add.v2.f32 [%0], {%1, %2};"
                             :: "l"(dst), "f"(a), "f"(bb) : "memory");
            }
    } else {
        float* dst = (which == 1) ? g_q : g_v;
        const float sc = (which == 1) ? LOG2E : 1.f;
        #pragma unroll
        for (int q = 0; q < 4; q++)
            #pragma unroll
            for (int p = 0; p < 8; p++) {
                float a, bb;
                upk2(a, bb, acc[q][p]);
                atomicAdd(&dst[((c0 + q) * 2048 + nbase + 2 * p + 0) * 2 + b], a * sc);
                atomicAdd(&dst[((c0 + q) * 2048 + nbase + 2 * p + 1) * 2 + b], bb * sc);
            }
    }
}

// =============================================================================
// Kernel B: per-column Z in log2 domain with BOX-BOUND shift (no max pass).
// REBALANCED: 64 cols per block, 64 threads -> 1024 blocks (~7/SM, 1.4% idle).
// grid (32 mchunk, c=32).
// =============================================================================
__global__ __launch_bounds__(64) void colstats_kernel()
{
    __shared__ float2 sq[2048];
    __shared__ float4 red[2];
    __shared__ float4 smm;
    const int t = threadIdx.x;
    const int c = blockIdx.y;
    const int m = blockIdx.x * 64 + t;

    const float2* qsrc = (const float2*)(g_q + c * 4096);
    float mxx = -1e30f, mnx = 1e30f, mxy = -1e30f, mny = 1e30f;
    for (int i = t; i < 2048; i += 64) {
        float2 q = qsrc[i];
        sq[i] = q;
        mxx = fmaxf(mxx, q.x); mnx = fminf(mnx, q.x);
        mxy = fmaxf(mxy, q.y); mny = fminf(mny, q.y);
    }
    #pragma unroll
    for (int off = 16; off; off >>= 1) {
        mxx = fmaxf(mxx, __shfl_xor_sync(~0u, mxx, off));
        mnx = fminf(mnx, __shfl_xor_sync(~0u, mnx, off));
        mxy = fmaxf(mxy, __shfl_xor_sync(~0u, mxy, off));
        mny = fminf(mny, __shfl_xor_sync(~0u, mny, off));
    }
    if ((t & 31) == 0) red[t >> 5] = make_float4(mxx, mnx, mxy, mny);
    __syncthreads();
    if (t == 0) {
        float4 a = red[0];
        float4 bb = red[1];
        a.x = fmaxf(a.x, bb.x); a.y = fminf(a.y, bb.y);
        a.z = fmaxf(a.z, bb.z); a.w = fminf(a.w, bb.w);
        smm = a;
    }
    __syncthreads();

    const float4 mm = smm;
    const float k0 = g_k[(c * 2 + 0) * 2048 + m];
    const float k1 = g_k[(c * 2 + 1) * 2048 + m];
    const float M = fmaxf(k0 * mm.x, k0 * mm.y) + fmaxf(k1 * mm.z, k1 * mm.w);

    float Z = 0.f;
    #pragma unroll 8
    for (int n = 0; n < 2048; n++) {
        float2 q = sq[n];
        float sv = fmaf(q.x, k0, fmaf(q.y, k1, -M));
        float e;
        asm("ex2.approx.ftz.f32 %0, %1;" : "=f"(e) : "f"(sv));
        Z += e;
    }
    const float invZ = 1.f / Z;
    g_nm[c * 2048 + m] = -M;
    g_vz[(c * 2048 + m) * 2 + 0] = g_v[(c * 2048 + m) * 2 + 0] * invZ;
    g_vz[(c * 2048 + m) * 2 + 1] = g_v[(c * 2048 + m) * 2 + 1] * invZ;
}

// =============================================================================
// Kernel C: out[c,n,b] += sum_{m in chunk} 2^(q.k - M) * vz[m,b]
// 8 n-rows per thread; m-chunks of 228 -> grid = 32c x 9m = 288 blocks.
// [R16 exact]
// =============================================================================
__global__ __launch_bounds__(256) void attn_out_kernel()
{
    __shared__ float4 ksm[228];   // (k0, k1, -M, pad)
    __shared__ float2 vzs[228];
    const int t   = threadIdx.x;
    const int bid = blockIdx.x;
    const int c   = bid / 9;
    const int mc  = bid % 9;
    const int m0  = mc * 228;
    const int mlen = (mc == 8) ? 224 : 228;

    if (t < mlen) {
        const int m = m0 + t;
        ksm[t] = make_float4(g_k[(c * 2 + 0) * 2048 + m],
                             g_k[(c * 2 + 1) * 2048 + m],
                             g_nm[c * 2048 + m], 0.f);
        vzs[t] = ((const float2*)(g_vz + c * 4096))[m];
    }
    __syncthreads();

    const float2* qsrc = (const float2*)(g_q + c * 4096);
    float2 q[8];
    #pragma unroll
    for (int r = 0; r < 8; r++) q[r] = qsrc[t + 256 * r];

    float ax[8], ay[8];
    #pragma unroll
    for (int r = 0; r < 8; r++) { ax[r] = 0.f; ay[r] = 0.f; }

    #pragma unroll 2
    for (int m = 0; m < mlen; m++) {
        const float4 kk = ksm[m];
        const float2 vv = vzs[m];
        #pragma unroll
        for (int r = 0; r < 8; r++) {
            float sv = fmaf(q[r].x, kk.x, fmaf(q[r].y, kk.y, kk.z));
            float e;
            asm("ex2.approx.ftz.f32 %0, %1;" : "=f"(e) : "f"(sv));
            ax[r] = fmaf(e, vv.x, ax[r]);
            ay[r] = fmaf(e, vv.y, ay[r]);
        }
    }

    float* dst = g_attn + c * 4096;
    #pragma unroll
    for (int r = 0; r < 8; r++) {
        float* p = dst + (t + 256 * r) * 2;
        asm volatile("red.global.add.v2.f32 [%0], {%1, %2};"
                     :: "l"(p), "f"(ax[r]), "f"(ay[r]) : "memory");
    }
}

// =============================================================================
// Kernel D: conv_alter (32 -> 64, 3x3x3, pad 1), split-K x8, CO-PAIRED, f32x2,
// precomputed fill + double buffer. [R16 exact]
// grid (cog=4, d=8, z=16: b*8+s), 128 threads = 8 slots x 16 h.
// =============================================================================
__global__ __launch_bounds__(128) void conv_alter_kernel(
    const float* __restrict__ wa, float* __restrict__ out)
{
    __shared__ float tile[2][1080];
    const int t   = threadIdx.x;
    const int b   = blockIdx.z >> 3;
    const int s   = blockIdx.z & 7;
    const int d   = blockIdx.y;
    const int cog = blockIdx.x;
    const int co0 = cog * 16 + (t >> 4) * 2;
    const int h   = t & 15;

    int  si[8], gb[8];
    #pragma unroll
    for (int j = 0; j < 8; j++) {
        const int i = t + j * 128;
        si[j] = 1078; gb[j] = 0;
        if (i < 972) {
            const int dd = i / 324, r = i % 324, hh = r / 18, ww = r % 18;
            const int gd = d + dd - 1, gh = hh - 1, gw = ww - 1;
            si[j] = dd * 360 + hh * 20 + ww;
            if ((unsigned)gd < 8u && (unsigned)gh < 16u && (unsigned)gw < 16u)
                gb[j] = (b * 32 + s * 4) * 2048 + gd * 256 + gh * 16 + gw + 1;
        }
    }

    u64 accA[8], accB[8];
    #pragma unroll
    for (int p = 0; p < 8; p++) { accA[p] = pk2(0.f, 0.f); accB[p] = pk2(0.f, 0.f); }
    const float* Wc0 = wa + co0 * 864 + s * 4 * 27;
    const float* Wc1 = Wc0 + 864;

    #pragma unroll
    for (int j = 0; j < 8; j++)
        tile[0][si[j]] = gb[j] ? g_attn[gb[j] - 1] : 0.f;
    __syncthreads();

    for (int ci = 0; ci < 4; ci++) {
        const int cur = ci & 1;
        float r[8];
        if (ci < 3) {
            const int off = (ci + 1) * 2048 - 1;
            #pragma unroll
            for (int j = 0; j < 8; j++)
                r[j] = gb[j] ? g_attn[gb[j] + off] : 0.f;
        }

        const float* W0i = Wc0 + ci * 27;
        const float* W1i = Wc1 + ci * 27;
        #pragma unroll
        for (int kd = 0; kd < 3; kd++) {
            #pragma unroll
            for (int kh = 0; kh < 3; kh++) {
                const float* row = &tile[cur][kd * 360 + (h + kh) * 20];
                u64 E[9], O[8];
                #pragma unroll
                for (int p = 0; p < 9; p++)
                    E[p] = *(const u64*)(row + 2 * p);
                #pragma unroll
                for (int p = 0; p < 8; p++) {
                    float elo, ehi, flo, fhi;
                    upk2(elo, ehi, E[p]);
                    upk2(flo, fhi, E[p + 1]);
                    O[p] = pk2(ehi, flo);
                }
                const int kb = (kd * 3 + kh) * 3;
                const u64 A0 = pk2(W0i[kb], W0i[kb]);
                const u64 A1 = pk2(W0i[kb + 1], W0i[kb + 1]);
                const u64 A2 = pk2(W0i[kb + 2], W0i[kb + 2]);
                const u64 B0 = pk2(W1i[kb], W1i[kb]);
                const u64 B1 = pk2(W1i[kb + 1], W1i[kb + 1]);
                const u64 B2 = pk2(W1i[kb + 2], W1i[kb + 2]);
                #pragma unroll
                for (int p = 0; p < 8; p++) {
                    accA[p] = fma2(A0, E[p], accA[p]);
                    accA[p] = fma2(A1, O[p], accA[p]);
                    accA[p] = fma2(A2, E[p + 1], accA[p]);
                    accB[p] = fma2(B0, E[p], accB[p]);
                    accB[p] = fma2(B1, O[p], accB[p]);
                    accB[p] = fma2(B2, E[p + 1], accB[p]);
                }
            }
        }

        if (ci < 3) {
            #pragma unroll
            for (int j = 0; j < 8; j++)
                tile[cur ^ 1][si[j]] = r[j];
        }
        __syncthreads();
    }

    const int nbase = d * 256 + h * 16;
    #pragma unroll
    for (int p = 0; p < 8; p++) {
        float a, bb;
        upk2(a, bb, accA[p]);
        float* dst = &out[(b * 64 + co0) * 2048 + nbase + 2 * p];
        asm volatile("red.global.add.v2.f32 [%0], {%1, %2};"
                     :: "l"(dst), "f"(a), "f"(bb) : "memory");
        upk2(a, bb, accB[p]);
        float* dst2 = &out[(b * 64 + co0 + 1) * 2048 + nbase + 2 * p];
        asm volatile("red.global.add.v2.f32 [%0], {%1, %2};"
                     :: "l"(dst2), "f"(a), "f"(bb) : "memory");
    }
}

// =============================================================================
extern "C" void kernel_launch(void* const* d_in, const int* in_sizes, int n_in,
                              void* d_out, int out_size)
{
    const float* x  = (const float*)d_in[0];
    const float* wk = (const float*)d_in[1];
    const float* bk = (const float*)d_in[2];
    const float* wq = (const float*)d_in[3];
    const float* bq = (const float*)d_in[4];
    const float* wv = (const float*)d_in[5];
    const float* bv = (const float*)d_in[6];
    const float* wa = (const float*)d_in[7];
    const float* ba = (const float*)d_in[8];
    float* out = (float*)d_out;

    init_kernel<<<512, 256>>>(x, bk, bq, bv, ba, out);
    conv_qkv_kernel<<<dim3(3, 8, 16), 128>>>(x, wk, wq, wv);
    colstats_kernel<<<dim3(32, 32), 64>>>();
    attn_out_kernel<<<288, 256>>>();
    conv_alter_kernel<<<dim3(4, 8, 16), 128>>>(wa, out);
}